// round 1
// baseline (speedup 1.0000x reference)
#include <cuda_runtime.h>
#include <math.h>

#define Bsz 128
#define Tlen 48
#define Dm 512
#define Mslots 64

// ---------------- scratch (static device globals; no allocation) -------------
__device__ float g_w[Bsz*Tlen*64];                 // logits -> softmax weights
__device__ unsigned long long g_code[Bsz*Tlen*2];  // packed iv codes (2b x 64)
__device__ int g_src[Bsz*Tlen];
__device__ float g_mem[Bsz*Mslots*Dm];             // value memory state
__device__ float g_read[Bsz*Dm];
__device__ float g_f[Bsz*Dm];
__device__ float g_we[Bsz*Dm];
__device__ float g_ft[Tlen*Bsz*Dm];                // f_t history (rows t*B+b)
__device__ float g_pre[Tlen*Bsz*2048];             // ft @ W_ih.T + b_ih
__device__ float g_H[(Tlen+1)*Bsz*Dm];
__device__ float g_C[(Tlen+1)*Bsz*Dm];

__device__ __forceinline__ float sigm(float x) { return 1.0f / (1.0f + expf(-x)); }

// ---------------- generic tiled GEMM: C = epi(A @ W^T + bias) ---------------
// tile: 16 rows x 32 cols, 128 threads, each thread 1x4 outputs.
// AMODE: 0 = k_table gather by q (rows flat b*T+t)
//        1 = concat(g_read, k_table[q[b,t]])  (rows = b)
//        2 = concat(g_f,   x_table[x[b,t]])   (rows = b)
//        3 = g_ft rows (flat t*B+b)
// EPI:   0 = store logits -> g_w
//        1 = tanh -> g_f and g_ft[t]
//        2 = raw + bias -> g_we
//        3 = raw + bias -> g_pre
template<int AMODE, int EPI>
__global__ void __launch_bounds__(128) k_gemm(
    const float* __restrict__ Wg, const float* __restrict__ bias,
    const float* __restrict__ ktab, const float* __restrict__ xtab,
    const int* __restrict__ qg, const int* __restrict__ rg,
    int N, int K, int t)
{
    __shared__ float As[16][33];
    __shared__ __align__(16) float Ws[32][36];
    const int tid = threadIdx.x;
    const int tx = tid & 7, ty = tid >> 3;
    const int row0 = blockIdx.x * 16;
    const int n0 = blockIdx.y * 32;
    float acc[4] = {0.f, 0.f, 0.f, 0.f};

    for (int k0 = 0; k0 < K; k0 += 32) {
#pragma unroll
        for (int i = 0; i < 4; i++) {
            int e = tid + i * 128;
            int rr = e >> 5, cc = e & 31;
            int row = row0 + rr;
            int kk = k0 + cc;
            float v;
            if (AMODE == 0)      v = ktab[qg[row] * Dm + kk];
            else if (AMODE == 1) v = (kk < Dm) ? g_read[row * Dm + kk]
                                               : ktab[qg[row * Tlen + t] * Dm + (kk - Dm)];
            else if (AMODE == 2) v = (kk < Dm) ? g_f[row * Dm + kk]
                                               : xtab[(qg[row * Tlen + t] + 2000 * rg[row * Tlen + t]) * Dm + (kk - Dm)];
            else                 v = g_ft[row * Dm + kk];
            As[rr][cc] = v;
        }
#pragma unroll
        for (int i = 0; i < 8; i++) {
            int e = tid + i * 128;
            int nn = e >> 5, cc = e & 31;
            Ws[cc][nn] = Wg[(n0 + nn) * K + (k0 + cc)];
        }
        __syncthreads();
#pragma unroll
        for (int c = 0; c < 32; c++) {
            float a = As[ty][c];
            float4 w4 = *reinterpret_cast<const float4*>(&Ws[c][tx * 4]);
            acc[0] = fmaf(a, w4.x, acc[0]);
            acc[1] = fmaf(a, w4.y, acc[1]);
            acc[2] = fmaf(a, w4.z, acc[2]);
            acc[3] = fmaf(a, w4.w, acc[3]);
        }
        __syncthreads();
    }
    const int row = row0 + ty;
#pragma unroll
    for (int j = 0; j < 4; j++) {
        int col = n0 + tx * 4 + j;
        float v = acc[j];
        if (EPI == 0) {
            g_w[row * 64 + col] = v;
        } else if (EPI == 1) {
            v = tanhf(v + bias[col]);
            g_f[row * Dm + col] = v;
            g_ft[(t * Bsz + row) * Dm + col] = v;
        } else if (EPI == 2) {
            g_we[row * Dm + col] = v + bias[col];
        } else {
            g_pre[row * 2048 + col] = v + bias[col];
        }
    }
}

// -------- softmax over 64 slots + triangular membership -> packed iv code ----
__global__ void __launch_bounds__(256) k_softmax_code()
{
    __shared__ unsigned char ivb[8][64];
    int wid = threadIdx.x >> 5, lane = threadIdx.x & 31;
    int bt = blockIdx.x * 8 + wid;
    float v0 = g_w[bt * 64 + lane];
    float v1 = g_w[bt * 64 + 32 + lane];
    float mx = fmaxf(v0, v1);
    for (int o = 16; o; o >>= 1) mx = fmaxf(mx, __shfl_xor_sync(0xffffffffu, mx, o));
    float e0 = expf(v0 - mx), e1 = expf(v1 - mx);
    float s = e0 + e1;
    for (int o = 16; o; o >>= 1) s += __shfl_xor_sync(0xffffffffu, s, o);
    float inv = 1.0f / s;
    float w0 = e0 * inv, w1 = e1 * inv;
    g_w[bt * 64 + lane] = w0;
    g_w[bt * 64 + 32 + lane] = w1;

    auto ivf = [](float w) -> int {
        float m = fmaxf(fminf((w - 0.075f) / (0.088f - 0.075f),
                              (1.0f - w) / (1.0f - 0.088f)), 0.0f);
        return (m >= 0.6f) ? 2 : ((m >= 0.1f) ? 1 : 0);
    };
    ivb[wid][lane] = (unsigned char)ivf(w0);
    ivb[wid][32 + lane] = (unsigned char)ivf(w1);
    __syncwarp();
    if (lane == 0) {
        unsigned long long c0 = 0ull, c1 = 0ull;
        for (int i = 0; i < 32; i++) {
            c0 |= (unsigned long long)ivb[wid][i] << (2 * i);
            c1 |= (unsigned long long)ivb[wid][32 + i] << (2 * i);
        }
        g_code[bt * 2] = c0;
        g_code[bt * 2 + 1] = c1;
    }
}

// ---- hop source: most recent j<i with identical iv code, else i-1 ----------
__global__ void __launch_bounds__(64) k_src()
{
    int b = blockIdx.x;
    int i = threadIdx.x;
    if (i >= Tlen) return;
    unsigned long long c0 = g_code[(b * Tlen + i) * 2];
    unsigned long long c1 = g_code[(b * Tlen + i) * 2 + 1];
    int s = i - 1;
    for (int j = i - 1; j >= 0; j--) {
        if (g_code[(b * Tlen + j) * 2] == c0 && g_code[(b * Tlen + j) * 2 + 1] == c1) { s = j; break; }
    }
    g_src[b * Tlen + i] = s;
}

// ---- init: broadcast Mv0 into mem, set H0/C0, compute read_0 ---------------
__global__ void __launch_bounds__(256) k_init(const float* __restrict__ Mv0,
                                              const float* __restrict__ hx0,
                                              const float* __restrict__ cx0)
{
    int gid = blockIdx.x * 256 + threadIdx.x;   // exactly B*M*D threads
    g_mem[gid] = Mv0[gid & (Mslots * Dm - 1)];
    if (gid < Bsz * Dm) {
        int b = gid >> 9, d = gid & 511;
        g_H[gid] = hx0[d];
        g_C[gid] = cx0[d];
        float s = 0.f;
        int wb = (b * Tlen) * 64;
        for (int m = 0; m < Mslots; m++) s = fmaf(g_w[wb + m], Mv0[m * Dm + d], s);
        g_read[gid] = s;
    }
}

// ---- e/a GEMMs + memory erase/add update + fused read_{t+1} ----------------
__global__ void __launch_bounds__(128) k_ea(const float* __restrict__ We, const float* __restrict__ be,
                                            const float* __restrict__ Wa, const float* __restrict__ ba,
                                            int t)
{
    __shared__ float As[16][33];
    __shared__ __align__(16) float WsE[32][36];
    __shared__ __align__(16) float WsA[32][36];
    __shared__ float es[16][33], aa[16][33];
    __shared__ float wsT[16][65], wsN[16][65];
    const int tid = threadIdx.x;
    const int tx = tid & 7, ty = tid >> 3;
    const int b0 = blockIdx.x * 16, d0 = blockIdx.y * 32;

    for (int i = tid; i < 16 * 64; i += 128) {
        int bl = i >> 6, m = i & 63;
        wsT[bl][m] = g_w[((b0 + bl) * Tlen + t) * 64 + m];
        wsN[bl][m] = (t + 1 < Tlen) ? g_w[((b0 + bl) * Tlen + t + 1) * 64 + m] : 0.0f;
    }

    float accE[4] = {0.f, 0.f, 0.f, 0.f}, accA[4] = {0.f, 0.f, 0.f, 0.f};
    for (int k0 = 0; k0 < Dm; k0 += 32) {
#pragma unroll
        for (int i = 0; i < 4; i++) {
            int e = tid + i * 128;
            int rr = e >> 5, cc = e & 31;
            As[rr][cc] = g_we[(b0 + rr) * Dm + k0 + cc];
        }
#pragma unroll
        for (int i = 0; i < 8; i++) {
            int e = tid + i * 128;
            int nn = e >> 5, cc = e & 31;
            WsE[cc][nn] = We[(d0 + nn) * Dm + k0 + cc];
            WsA[cc][nn] = Wa[(d0 + nn) * Dm + k0 + cc];
        }
        __syncthreads();
#pragma unroll
        for (int c = 0; c < 32; c++) {
            float a = As[ty][c];
            float4 w4 = *reinterpret_cast<const float4*>(&WsE[c][tx * 4]);
            float4 u4 = *reinterpret_cast<const float4*>(&WsA[c][tx * 4]);
            accE[0] = fmaf(a, w4.x, accE[0]); accE[1] = fmaf(a, w4.y, accE[1]);
            accE[2] = fmaf(a, w4.z, accE[2]); accE[3] = fmaf(a, w4.w, accE[3]);
            accA[0] = fmaf(a, u4.x, accA[0]); accA[1] = fmaf(a, u4.y, accA[1]);
            accA[2] = fmaf(a, u4.z, accA[2]); accA[3] = fmaf(a, u4.w, accA[3]);
        }
        __syncthreads();
    }
#pragma unroll
    for (int j = 0; j < 4; j++) {
        int col = d0 + tx * 4 + j;
        es[ty][tx * 4 + j] = sigm(accE[j] + be[col]);
        aa[ty][tx * 4 + j] = tanhf(accA[j] + ba[col]);
    }
    __syncthreads();

    // mem update + accumulate read_{t+1}; thread owns (b, d-quad) across all m
    int bl = tid >> 3, d4 = tid & 7;
    int b = b0 + bl;
    float ev[4], av[4];
#pragma unroll
    for (int j = 0; j < 4; j++) { ev[j] = es[bl][d4 * 4 + j]; av[j] = aa[bl][d4 * 4 + j]; }
    float r0 = 0.f, r1 = 0.f, r2 = 0.f, r3 = 0.f;
    for (int m = 0; m < Mslots; m++) {
        float wt = wsT[bl][m], wn = wsN[bl][m];
        float4* p = reinterpret_cast<float4*>(&g_mem[(b * Mslots + m) * Dm + d0 + d4 * 4]);
        float4 v = *p;
        v.x = v.x * (1.0f - wt * ev[0]) + wt * av[0];
        v.y = v.y * (1.0f - wt * ev[1]) + wt * av[1];
        v.z = v.z * (1.0f - wt * ev[2]) + wt * av[2];
        v.w = v.w * (1.0f - wt * ev[3]) + wt * av[3];
        *p = v;
        r0 = fmaf(wn, v.x, r0); r1 = fmaf(wn, v.y, r1);
        r2 = fmaf(wn, v.z, r2); r3 = fmaf(wn, v.w, r3);
    }
    float4* rp = reinterpret_cast<float4*>(&g_read[b * Dm + d0 + d4 * 4]);
    *rp = make_float4(r0, r1, r2, r3);
}

// ---- hop-LSTM step: all 4 gate quarters for a j-tile, then finalize --------
__global__ void __launch_bounds__(128) k_lstm(const float* __restrict__ Whh,
                                              const float* __restrict__ bhh, int t)
{
    __shared__ float As[16][33];
    __shared__ __align__(16) float Ws[4][32][36];
    __shared__ int s16[16];
    const int tid = threadIdx.x;
    const int tx = tid & 7, ty = tid >> 3;
    const int b0 = blockIdx.x * 16, j0 = blockIdx.y * 32;
    if (tid < 16) s16[tid] = g_src[(b0 + tid) * Tlen + t] + 1;
    __syncthreads();

    float acc[4][4] = {};
    for (int k0 = 0; k0 < Dm; k0 += 32) {
#pragma unroll
        for (int i = 0; i < 4; i++) {
            int e = tid + i * 128;
            int rr = e >> 5, cc = e & 31;
            As[rr][cc] = g_H[(s16[rr] * Bsz + b0 + rr) * Dm + k0 + cc];
        }
#pragma unroll
        for (int i = 0; i < 32; i++) {
            int e = tid + i * 128;
            int qd = e >> 10, rem = e & 1023;
            int nn = rem >> 5, cc = rem & 31;
            Ws[qd][cc][nn] = Whh[(qd * Dm + j0 + nn) * Dm + k0 + cc];
        }
        __syncthreads();
#pragma unroll
        for (int c = 0; c < 32; c++) {
            float a = As[ty][c];
#pragma unroll
            for (int qd = 0; qd < 4; qd++) {
                float4 w4 = *reinterpret_cast<const float4*>(&Ws[qd][c][tx * 4]);
                acc[qd][0] = fmaf(a, w4.x, acc[qd][0]);
                acc[qd][1] = fmaf(a, w4.y, acc[qd][1]);
                acc[qd][2] = fmaf(a, w4.z, acc[qd][2]);
                acc[qd][3] = fmaf(a, w4.w, acc[qd][3]);
            }
        }
        __syncthreads();
    }
    const int b = b0 + ty;
    const int pb = (t * Bsz + b) * 2048;
    const int src1 = s16[ty];
#pragma unroll
    for (int j = 0; j < 4; j++) {
        int col = j0 + tx * 4 + j;
        float gi = acc[0][j] + g_pre[pb + col] + bhh[col];
        float gf = acc[1][j] + g_pre[pb + 512 + col] + bhh[512 + col];
        float gg = acc[2][j] + g_pre[pb + 1024 + col] + bhh[1024 + col];
        float go = acc[3][j] + g_pre[pb + 1536 + col] + bhh[1536 + col];
        float cin = g_C[(src1 * Bsz + b) * Dm + col];
        float cnew = sigm(gf) * cin + sigm(gi) * tanhf(gg);
        float hnew = sigm(go) * tanhf(cnew);
        g_C[((t + 1) * Bsz + b) * Dm + col] = cnew;
        g_H[((t + 1) * Bsz + b) * Dm + col] = hnew;
    }
}

// ---- prediction head: p[b,t] = sigmoid(h_{t}[b] . W_p + b_p) ---------------
__global__ void __launch_bounds__(256) k_head(const float* __restrict__ Wp,
                                              const float* __restrict__ bp,
                                              float* __restrict__ out)
{
    int wid = threadIdx.x >> 5, lane = threadIdx.x & 31;
    int bt = blockIdx.x * 8 + wid;
    int b = bt / Tlen, t = bt % Tlen;
    const float* h = &g_H[((t + 1) * Bsz + b) * Dm];
    float s = 0.f;
    for (int i = lane; i < Dm; i += 32) s = fmaf(h[i], Wp[i], s);
    for (int o = 16; o; o >>= 1) s += __shfl_xor_sync(0xffffffffu, s, o);
    if (lane == 0) out[bt] = sigm(s + bp[0]);
}

// ----------------------------------------------------------------------------
extern "C" void kernel_launch(void* const* d_in, const int* in_sizes, int n_in,
                              void* d_out, int out_size)
{
    const int*   q    = (const int*)d_in[0];
    const int*   r    = (const int*)d_in[1];
    const float* Mk   = (const float*)d_in[2];
    const float* Mv0  = (const float*)d_in[3];
    const float* ktab = (const float*)d_in[4];
    const float* xtab = (const float*)d_in[5];
    const float* We   = (const float*)d_in[6];
    const float* be   = (const float*)d_in[7];
    const float* Wadd = (const float*)d_in[8];
    const float* badd = (const float*)d_in[9];
    const float* Wa   = (const float*)d_in[10];
    const float* ba   = (const float*)d_in[11];
    const float* Wf   = (const float*)d_in[12];
    const float* bf   = (const float*)d_in[13];
    const float* Wih  = (const float*)d_in[14];
    const float* Whh  = (const float*)d_in[15];
    const float* bih  = (const float*)d_in[16];
    const float* bhh  = (const float*)d_in[17];
    const float* hx0  = (const float*)d_in[18];
    const float* cx0  = (const float*)d_in[19];
    const float* Wp   = (const float*)d_in[20];
    const float* bp   = (const float*)d_in[21];
    float* out = (float*)d_out;

    // addressing logits (B*T x 64) = k_table[q] @ Mk^T
    k_gemm<0, 0><<<dim3(384, 2), 128>>>(Mk, nullptr, ktab, xtab, q, r, 64, 512, 0);
    // softmax + iv codes, then hop sources
    k_softmax_code<<<768, 256>>>();
    k_src<<<128, 64>>>();
    // init memory, H0/C0, read_0
    k_init<<<16384, 256>>>(Mv0, hx0, cx0);

    // ---- memory recurrence: 48 steps x 3 kernels ----
    for (int t = 0; t < Tlen; t++) {
        k_gemm<1, 1><<<dim3(8, 16), 128>>>(Wf, bf, ktab, xtab, q, r, 512, 1024, t);
        k_gemm<2, 2><<<dim3(8, 16), 128>>>(Wa, ba, ktab, xtab, q, r, 512, 1024, t);
        k_ea<<<dim3(8, 16), 128>>>(We, be, Wadd, badd, t);
    }

    // ---- hoisted input-gate GEMM: g_pre = ft @ W_ih^T + b_ih ----
    k_gemm<3, 3><<<dim3(384, 64), 128>>>(Wih, bih, ktab, xtab, q, r, 2048, 512, 0);

    // ---- hop-LSTM: 48 sequential steps ----
    for (int t = 0; t < Tlen; t++) {
        k_lstm<<<dim3(8, 16), 128>>>(Whh, bhh, t);
    }

    // ---- head ----
    k_head<<<768, 256>>>(Wp, bp, out);
}

// round 2
// speedup vs baseline: 1.2909x; 1.2909x over previous
#include <cuda_runtime.h>
#include <math.h>

#define Bsz 128
#define Tlen 48
#define Dm 512
#define Mslots 64
#define NBLK 128
#define NTHR 512

// ---------------- scratch (static device globals; no allocation) -------------
__device__ float g_w[Bsz*Tlen*64];                 // softmax weights
__device__ unsigned long long g_code[Bsz*Tlen*2];  // packed iv codes
__device__ int g_src[Bsz*Tlen];
__device__ float g_mem[Bsz*Mslots*Dm];
__device__ float g_read[Bsz*Dm];
__device__ float g_f[Bsz*Dm];
__device__ float g_we[Bsz*Dm];
__device__ float g_ft[Tlen*Bsz*Dm];
__device__ float g_pre[Tlen*Bsz*2048];
__device__ float g_H[(Tlen+1)*Bsz*Dm];
__device__ float g_C[(Tlen+1)*Bsz*Dm];

__device__ unsigned g_count = 0;
__device__ unsigned g_sense = 0;

__device__ __forceinline__ float sigm(float x) { return 1.0f / (1.0f + expf(-x)); }

// ---------------- shared memory layout for the persistent kernel -------------
struct Smem {
    __align__(16) float As[4][16][33];   // 2112 floats (also reused as [64][33] in pre stage)
    __align__(16) float Ws[4][32][36];   // 4608
    __align__(16) float part[4][16][36]; // 2304
    float wsT[16][64];                   // 1024
    float wsN[16][64];                   // 1024
    int   s16[16];
};

// ---------------- grid-wide sense-reversal barrier ---------------------------
__device__ __forceinline__ void gsync(unsigned& lsense) {
    __syncthreads();
    if (threadIdx.x == 0) {
        unsigned target = lsense ^ 1u;
        __threadfence();                       // release (gpu scope -> CCTL.IVALL)
        unsigned arrived = atomicAdd(&g_count, 1u);
        if (arrived == gridDim.x - 1) {
            atomicExch(&g_count, 0u);
            __threadfence();
            atomicExch(&g_sense, target);
        } else {
            while (atomicAdd(&g_sense, 0u) != target) { }
        }
        lsense = target;
        __threadfence();                       // acquire
    }
    __syncthreads();
}

// ---------------- persistent-kernel stages -----------------------------------
// f / we GEMM: C[128,512] = epi([X | tab[idx]] @ W^T + bias), K=1024, split-K x4
template<int MODE>  // 0: f = tanh(...), X=g_read, tab=ktab ; 1: we = raw, X=g_f, tab=xtab
__device__ void stage_fwe(Smem& s, const float* __restrict__ W, const float* __restrict__ bias,
                          const float* __restrict__ tab, const int* __restrict__ q,
                          const int* __restrict__ r, int t, int r0, int c0)
{
    const int tid = threadIdx.x;
    const int g = tid >> 7, gt = tid & 127;
    const int ty = gt >> 3, tx = gt & 7;
    float a0 = 0.f, a1 = 0.f, a2 = 0.f, a3 = 0.f;
    const int kbase0 = g * 256;
    for (int kt = 0; kt < 8; kt++) {
        const int kb = kbase0 + kt * 32;
#pragma unroll
        for (int i = 0; i < 4; i++) {
            int e = gt + i * 128;
            int rr = e >> 5, cc = e & 31;
            int b = r0 + rr, kk = kb + cc;
            float v;
            if (kk < Dm) {
                v = (MODE == 0) ? __ldcg(&g_read[b * Dm + kk]) : __ldcg(&g_f[b * Dm + kk]);
            } else {
                int idx = (MODE == 0) ? q[b * Tlen + t]
                                      : (q[b * Tlen + t] + 2000 * r[b * Tlen + t]);
                v = tab[idx * Dm + (kk - Dm)];
            }
            s.As[g][rr][cc] = v;
        }
#pragma unroll
        for (int i = 0; i < 8; i++) {
            int e = gt + i * 128;
            int nn = e >> 5, cc = e & 31;
            s.Ws[g][cc][nn] = W[(c0 + nn) * 1024 + kb + cc];
        }
        __syncthreads();
#pragma unroll
        for (int c = 0; c < 32; c++) {
            float a = s.As[g][ty][c];
            float4 w4 = *reinterpret_cast<const float4*>(&s.Ws[g][c][tx * 4]);
            a0 = fmaf(a, w4.x, a0); a1 = fmaf(a, w4.y, a1);
            a2 = fmaf(a, w4.z, a2); a3 = fmaf(a, w4.w, a3);
        }
        __syncthreads();
    }
    *reinterpret_cast<float4*>(&s.part[g][ty][tx * 4]) = make_float4(a0, a1, a2, a3);
    __syncthreads();
    const int rr = tid >> 5, cc = tid & 31;
    float v = s.part[0][rr][cc] + s.part[1][rr][cc] + s.part[2][rr][cc] + s.part[3][rr][cc]
            + bias[c0 + cc];
    const int b = r0 + rr;
    if (MODE == 0) {
        v = tanhf(v);
        g_f[b * Dm + c0 + cc] = v;
        g_ft[(t * Bsz + b) * Dm + c0 + cc] = v;
    } else {
        g_we[b * Dm + c0 + cc] = v;
    }
}

// e/a GEMMs (K=512 each, 2 groups per GEMM) + erase/add update + fused read_{t+1}
__device__ void stage_ea(Smem& s, const float* __restrict__ We, const float* __restrict__ be,
                         const float* __restrict__ Wa, const float* __restrict__ ba,
                         int t, int r0, int c0)
{
    const int tid = threadIdx.x;
    const int g = tid >> 7, gt = tid & 127;
    const int ty = gt >> 3, tx = gt & 7;
    const int kh = g & 1;
    const float* W = (g >> 1) ? Wa : We;

    // stage the addressing weights for this step and the next
    for (int i = tid; i < 16 * 64; i += NTHR) {
        int bl = i >> 6, m = i & 63;
        s.wsT[bl][m] = g_w[((r0 + bl) * Tlen + t) * 64 + m];
        s.wsN[bl][m] = (t + 1 < Tlen) ? g_w[((r0 + bl) * Tlen + t + 1) * 64 + m] : 0.0f;
    }

    float a0 = 0.f, a1 = 0.f, a2 = 0.f, a3 = 0.f;
    for (int kt = 0; kt < 8; kt++) {
        const int kb = kh * 256 + kt * 32;
#pragma unroll
        for (int i = 0; i < 4; i++) {
            int e = gt + i * 128;
            int rr = e >> 5, cc = e & 31;
            s.As[g][rr][cc] = __ldcg(&g_we[(r0 + rr) * Dm + kb + cc]);
        }
#pragma unroll
        for (int i = 0; i < 8; i++) {
            int e = gt + i * 128;
            int nn = e >> 5, cc = e & 31;
            s.Ws[g][cc][nn] = W[(c0 + nn) * Dm + kb + cc];
        }
        __syncthreads();
#pragma unroll
        for (int c = 0; c < 32; c++) {
            float a = s.As[g][ty][c];
            float4 w4 = *reinterpret_cast<const float4*>(&s.Ws[g][c][tx * 4]);
            a0 = fmaf(a, w4.x, a0); a1 = fmaf(a, w4.y, a1);
            a2 = fmaf(a, w4.z, a2); a3 = fmaf(a, w4.w, a3);
        }
        __syncthreads();
    }
    *reinterpret_cast<float4*>(&s.part[g][ty][tx * 4]) = make_float4(a0, a1, a2, a3);
    __syncthreads();
    const int rr = tid >> 5, cc = tid & 31;
    float ev = sigm(s.part[0][rr][cc] + s.part[1][rr][cc] + be[c0 + cc]);
    float av = tanhf(s.part[2][rr][cc] + s.part[3][rr][cc] + ba[c0 + cc]);
    __syncthreads();
    s.part[0][rr][cc] = ev;
    s.part[1][rr][cc] = av;
    __syncthreads();

    // memory update + read_{t+1}; thread owns (b = r0+bl, d = c0+dd), loops m
    const int bl = tid >> 5, dd = tid & 31;
    const int b = r0 + bl;
    const float e = s.part[0][bl][dd];
    const float a = s.part[1][bl][dd];
    float racc = 0.f;
    const int base = b * Mslots * Dm + c0 + dd;
#pragma unroll 4
    for (int m = 0; m < Mslots; m++) {
        float wt = s.wsT[bl][m], wn = s.wsN[bl][m];
        float* p = &g_mem[base + m * Dm];
        float v = *p;
        v = v * (1.0f - wt * e) + wt * a;
        *p = v;
        racc = fmaf(wn, v, racc);
    }
    g_read[b * Dm + c0 + dd] = racc;
}

// big hoisted GEMM: g_pre[6144,2048] = g_ft @ Wih^T + b_ih  (tiles 64x32)
__device__ void stage_pre(Smem& s, const float* __restrict__ Wih, const float* __restrict__ bih)
{
    const int tid = threadIdx.x;
    const int tyy = tid >> 3;   // row in tile (0..63)
    const int txx = tid & 7;    // 4 cols
    float* As64 = &s.As[0][0][0];   // [64][33]
    for (int tile = blockIdx.x; tile < 96 * 64; tile += NBLK) {
        const int row0 = (tile >> 6) * 64;
        const int cc0 = (tile & 63) * 32;
        float a0 = 0.f, a1 = 0.f, a2 = 0.f, a3 = 0.f;
        for (int kt = 0; kt < 16; kt++) {
            const int kb = kt * 32;
#pragma unroll
            for (int i = 0; i < 4; i++) {
                int e = tid + i * 512;
                int rr = e >> 5, cc = e & 31;
                As64[rr * 33 + cc] = __ldcg(&g_ft[(row0 + rr) * Dm + kb + cc]);
            }
#pragma unroll
            for (int i = 0; i < 2; i++) {
                int e = tid + i * 512;
                int nn = e >> 5, cc = e & 31;
                s.Ws[0][cc][nn] = Wih[(cc0 + nn) * Dm + kb + cc];
            }
            __syncthreads();
#pragma unroll
            for (int c = 0; c < 32; c++) {
                float a = As64[tyy * 33 + c];
                float4 w4 = *reinterpret_cast<const float4*>(&s.Ws[0][c][txx * 4]);
                a0 = fmaf(a, w4.x, a0); a1 = fmaf(a, w4.y, a1);
                a2 = fmaf(a, w4.z, a2); a3 = fmaf(a, w4.w, a3);
            }
            __syncthreads();
        }
        const int row = row0 + tyy;
        float4 o4 = make_float4(a0 + bih[cc0 + txx * 4 + 0], a1 + bih[cc0 + txx * 4 + 1],
                                a2 + bih[cc0 + txx * 4 + 2], a3 + bih[cc0 + txx * 4 + 3]);
        *reinterpret_cast<float4*>(&g_pre[row * 2048 + cc0 + txx * 4]) = o4;
    }
}

// hop-LSTM step: hh GEMM (4 gate quarters, one per group) + fused finalize
__device__ void stage_lstm(Smem& s, const float* __restrict__ Whh,
                           const float* __restrict__ bhh, int t, int r0, int j0)
{
    const int tid = threadIdx.x;
    const int g = tid >> 7, gt = tid & 127;
    const int ty = gt >> 3, tx = gt & 7;
    if (tid < 16) s.s16[tid] = g_src[(r0 + tid) * Tlen + t] + 1;
    __syncthreads();

    float a0 = 0.f, a1 = 0.f, a2 = 0.f, a3 = 0.f;
    for (int kt = 0; kt < 16; kt++) {
        const int kb = kt * 32;
        {
            int rr = tid >> 5, cc = tid & 31;
            s.As[0][rr][cc] = __ldcg(&g_H[(s.s16[rr] * Bsz + r0 + rr) * Dm + kb + cc]);
        }
#pragma unroll
        for (int i = 0; i < 8; i++) {
            int e = gt + i * 128;
            int nn = e >> 5, cc = e & 31;
            s.Ws[g][cc][nn] = Whh[(g * Dm + j0 + nn) * Dm + kb + cc];
        }
        __syncthreads();
#pragma unroll
        for (int c = 0; c < 32; c++) {
            float a = s.As[0][ty][c];
            float4 w4 = *reinterpret_cast<const float4*>(&s.Ws[g][c][tx * 4]);
            a0 = fmaf(a, w4.x, a0); a1 = fmaf(a, w4.y, a1);
            a2 = fmaf(a, w4.z, a2); a3 = fmaf(a, w4.w, a3);
        }
        __syncthreads();
    }
    *reinterpret_cast<float4*>(&s.part[g][ty][tx * 4]) = make_float4(a0, a1, a2, a3);
    __syncthreads();

    const int rr = tid >> 5, cc = tid & 31;
    const int b = r0 + rr, col = j0 + cc;
    const float* pre = &g_pre[(t * Bsz + b) * 2048];
    float gi = s.part[0][rr][cc] + __ldcg(&pre[col])        + bhh[col];
    float gf = s.part[1][rr][cc] + __ldcg(&pre[512 + col])  + bhh[512 + col];
    float gg = s.part[2][rr][cc] + __ldcg(&pre[1024 + col]) + bhh[1024 + col];
    float go = s.part[3][rr][cc] + __ldcg(&pre[1536 + col]) + bhh[1536 + col];
    const int src1 = s.s16[rr];
    float cin = __ldcg(&g_C[(src1 * Bsz + b) * Dm + col]);
    float cnew = sigm(gf) * cin + sigm(gi) * tanhf(gg);
    float hnew = sigm(go) * tanhf(cnew);
    g_C[((t + 1) * Bsz + b) * Dm + col] = cnew;
    g_H[((t + 1) * Bsz + b) * Dm + col] = hnew;
}

__device__ void stage_head(const float* __restrict__ Wp, const float* __restrict__ bp,
                           float* __restrict__ out)
{
    const int wid = threadIdx.x >> 5, lane = threadIdx.x & 31;
    for (int bt = blockIdx.x * 16 + wid; bt < Bsz * Tlen; bt += NBLK * 16) {
        const int b = bt / Tlen, t = bt % Tlen;
        const float* h = &g_H[((t + 1) * Bsz + b) * Dm];
        float sacc = 0.f;
        for (int i = lane; i < Dm; i += 32) sacc = fmaf(__ldcg(&h[i]), Wp[i], sacc);
        for (int o = 16; o; o >>= 1) sacc += __shfl_xor_sync(0xffffffffu, sacc, o);
        if (lane == 0) out[bt] = sigm(sacc + bp[0]);
    }
}

// ---------------- the persistent kernel --------------------------------------
__global__ void __launch_bounds__(NTHR, 1) k_persist(
    const int* __restrict__ q, const int* __restrict__ r,
    const float* __restrict__ ktab, const float* __restrict__ xtab,
    const float* __restrict__ Wf, const float* __restrict__ bf,
    const float* __restrict__ Wa, const float* __restrict__ ba,
    const float* __restrict__ We, const float* __restrict__ be,
    const float* __restrict__ Wadd, const float* __restrict__ badd,
    const float* __restrict__ Wih, const float* __restrict__ bih,
    const float* __restrict__ Whh, const float* __restrict__ bhh,
    const float* __restrict__ Wp, const float* __restrict__ bp,
    float* __restrict__ out)
{
    __shared__ Smem s;
    unsigned lsense = 0;
    if (threadIdx.x == 0) lsense = atomicAdd(&g_sense, 0u);
    const int r0 = (blockIdx.x & 7) * 16;
    const int c0 = (blockIdx.x >> 3) * 32;

    for (int t = 0; t < Tlen; t++) {
        stage_fwe<0>(s, Wf, bf, ktab, q, r, t, r0, c0);   gsync(lsense);
        stage_fwe<1>(s, Wa, ba, xtab, q, r, t, r0, c0);   gsync(lsense);
        stage_ea(s, We, be, Wadd, badd, t, r0, c0);       gsync(lsense);
    }
    stage_pre(s, Wih, bih);                               gsync(lsense);
    for (int t = 0; t < Tlen; t++) {
        stage_lstm(s, Whh, bhh, t, r0, c0);               gsync(lsense);
    }
    stage_head(Wp, bp, out);
}

// ---------------- prologue kernels (parallel, cheap) -------------------------
__global__ void __launch_bounds__(128) k_addr(const float* __restrict__ Mk,
                                              const float* __restrict__ ktab,
                                              const int* __restrict__ q)
{
    __shared__ float As[16][33];
    __shared__ __align__(16) float Ws[32][36];
    const int tid = threadIdx.x;
    const int tx = tid & 7, ty = tid >> 3;
    const int row0 = blockIdx.x * 16;
    const int n0 = blockIdx.y * 32;
    float acc[4] = {0.f, 0.f, 0.f, 0.f};
    for (int k0 = 0; k0 < Dm; k0 += 32) {
#pragma unroll
        for (int i = 0; i < 4; i++) {
            int e = tid + i * 128;
            int rr = e >> 5, cc = e & 31;
            As[rr][cc] = ktab[q[row0 + rr] * Dm + k0 + cc];
        }
#pragma unroll
        for (int i = 0; i < 8; i++) {
            int e = tid + i * 128;
            int nn = e >> 5, cc = e & 31;
            Ws[cc][nn] = Mk[(n0 + nn) * Dm + (k0 + cc)];
        }
        __syncthreads();
#pragma unroll
        for (int c = 0; c < 32; c++) {
            float a = As[ty][c];
            float4 w4 = *reinterpret_cast<const float4*>(&Ws[c][tx * 4]);
            acc[0] = fmaf(a, w4.x, acc[0]); acc[1] = fmaf(a, w4.y, acc[1]);
            acc[2] = fmaf(a, w4.z, acc[2]); acc[3] = fmaf(a, w4.w, acc[3]);
        }
        __syncthreads();
    }
#pragma unroll
    for (int j = 0; j < 4; j++)
        g_w[(row0 + ty) * 64 + n0 + tx * 4 + j] = acc[j];
}

__global__ void __launch_bounds__(256) k_softmax_code()
{
    __shared__ unsigned char ivb[8][64];
    int wid = threadIdx.x >> 5, lane = threadIdx.x & 31;
    int bt = blockIdx.x * 8 + wid;
    float v0 = g_w[bt * 64 + lane];
    float v1 = g_w[bt * 64 + 32 + lane];
    float mx = fmaxf(v0, v1);
    for (int o = 16; o; o >>= 1) mx = fmaxf(mx, __shfl_xor_sync(0xffffffffu, mx, o));
    float e0 = expf(v0 - mx), e1 = expf(v1 - mx);
    float ssum = e0 + e1;
    for (int o = 16; o; o >>= 1) ssum += __shfl_xor_sync(0xffffffffu, ssum, o);
    float inv = 1.0f / ssum;
    float w0 = e0 * inv, w1 = e1 * inv;
    g_w[bt * 64 + lane] = w0;
    g_w[bt * 64 + 32 + lane] = w1;

    auto ivf = [](float w) -> int {
        float m = fmaxf(fminf((w - 0.075f) / (0.088f - 0.075f),
                              (1.0f - w) / (1.0f - 0.088f)), 0.0f);
        return (m >= 0.6f) ? 2 : ((m >= 0.1f) ? 1 : 0);
    };
    ivb[wid][lane] = (unsigned char)ivf(w0);
    ivb[wid][32 + lane] = (unsigned char)ivf(w1);
    __syncwarp();
    if (lane == 0) {
        unsigned long long c0 = 0ull, c1 = 0ull;
        for (int i = 0; i < 32; i++) {
            c0 |= (unsigned long long)ivb[wid][i] << (2 * i);
            c1 |= (unsigned long long)ivb[wid][32 + i] << (2 * i);
        }
        g_code[bt * 2] = c0;
        g_code[bt * 2 + 1] = c1;
    }
}

__global__ void __launch_bounds__(64) k_src()
{
    int b = blockIdx.x;
    int i = threadIdx.x;
    if (i >= Tlen) return;
    unsigned long long c0 = g_code[(b * Tlen + i) * 2];
    unsigned long long c1 = g_code[(b * Tlen + i) * 2 + 1];
    int s = i - 1;
    for (int j = i - 1; j >= 0; j--) {
        if (g_code[(b * Tlen + j) * 2] == c0 && g_code[(b * Tlen + j) * 2 + 1] == c1) { s = j; break; }
    }
    g_src[b * Tlen + i] = s;
}

__global__ void __launch_bounds__(256) k_init(const float* __restrict__ Mv0,
                                              const float* __restrict__ hx0,
                                              const float* __restrict__ cx0)
{
    int gid = blockIdx.x * 256 + threadIdx.x;   // exactly B*M*D threads
    g_mem[gid] = Mv0[gid & (Mslots * Dm - 1)];
    if (gid < Bsz * Dm) {
        int b = gid >> 9, d = gid & 511;
        g_H[gid] = hx0[d];
        g_C[gid] = cx0[d];
        float s = 0.f;
        int wb = (b * Tlen) * 64;
        for (int m = 0; m < Mslots; m++) s = fmaf(g_w[wb + m], Mv0[m * Dm + d], s);
        g_read[gid] = s;
    }
}

// ----------------------------------------------------------------------------
extern "C" void kernel_launch(void* const* d_in, const int* in_sizes, int n_in,
                              void* d_out, int out_size)
{
    const int*   q    = (const int*)d_in[0];
    const int*   r    = (const int*)d_in[1];
    const float* Mk   = (const float*)d_in[2];
    const float* Mv0  = (const float*)d_in[3];
    const float* ktab = (const float*)d_in[4];
    const float* xtab = (const float*)d_in[5];
    const float* We   = (const float*)d_in[6];
    const float* be   = (const float*)d_in[7];
    const float* Wadd = (const float*)d_in[8];
    const float* badd = (const float*)d_in[9];
    const float* Wa   = (const float*)d_in[10];
    const float* ba   = (const float*)d_in[11];
    const float* Wf   = (const float*)d_in[12];
    const float* bf   = (const float*)d_in[13];
    const float* Wih  = (const float*)d_in[14];
    const float* Whh  = (const float*)d_in[15];
    const float* bih  = (const float*)d_in[16];
    const float* bhh  = (const float*)d_in[17];
    const float* hx0  = (const float*)d_in[18];
    const float* cx0  = (const float*)d_in[19];
    const float* Wp   = (const float*)d_in[20];
    const float* bp   = (const float*)d_in[21];
    float* out = (float*)d_out;

    k_addr<<<dim3(384, 2), 128>>>(Mk, ktab, q);
    k_softmax_code<<<768, 256>>>();
    k_src<<<128, 64>>>();
    k_init<<<16384, 256>>>(Mv0, hx0, cx0);
    k_persist<<<NBLK, NTHR>>>(q, r, ktab, xtab, Wf, bf, Wa, ba, We, be, Wadd, badd,
                              Wih, bih, Whh, bhh, Wp, bp, out);
}

// round 3
// speedup vs baseline: 1.9552x; 1.5147x over previous
#include <cuda_runtime.h>
#include <math.h>

#define Bsz 128
#define Tlen 48
#define Dm 512
#define NBLK 128
#define NTHR 512

// ---------------- global scratch ---------------------------------------------
__device__ float g_w[Bsz*Tlen*64];
__device__ unsigned long long g_code[Bsz*Tlen*2];
__device__ int g_src[Bsz*Tlen];
__device__ float g_read[Bsz*Dm];
__device__ float g_f[Bsz*Dm];
__device__ float g_we[Bsz*Dm];
__device__ float g_ft[Tlen*Bsz*Dm];
__device__ float g_H[(Tlen+1)*Bsz*Dm];
__device__ float g_C[(Tlen+1)*Bsz*Dm];
__device__ unsigned g_count = 0;
__device__ volatile unsigned g_sense = 0;

__device__ __forceinline__ float sigm(float x) { return 1.0f / (1.0f + expf(-x)); }

// smem layout (floats): [0,32768) memS | [32768,+2560) As | [35328,+4608) Ws
// [39936,+9216) part | [49152,+1024) wT | [50176,+1024) wN | [51200,+16) ints
#define OFF_AS   32768
#define OFF_WS   35328
#define OFF_PART 39936
#define OFF_WT   49152
#define OFF_WN   50176
#define OFF_I16  51200
#define SMEM_FLOATS 51232
#define SMEM_BYTES (SMEM_FLOATS * 4)

// ---------------- grid-wide barrier (volatile-load poll) ---------------------
__device__ __forceinline__ void gsync(unsigned& ls) {
    __syncthreads();
    if (threadIdx.x == 0) {
        unsigned target = ls ^ 1u;
        __threadfence();                              // release
        if (atomicAdd(&g_count, 1u) == gridDim.x - 1) {
            atomicExch(&g_count, 0u);
            __threadfence();
            g_sense = target;
        } else {
            while (g_sense != target) { }
        }
        ls = target;
        __threadfence();                              // acquire (CCTL.IVALL)
    }
    __syncthreads();
}

__device__ __forceinline__ void fma16(float (&acc)[4][4], float4 a, float4 w) {
    acc[0][0]=fmaf(a.x,w.x,acc[0][0]); acc[0][1]=fmaf(a.x,w.y,acc[0][1]);
    acc[0][2]=fmaf(a.x,w.z,acc[0][2]); acc[0][3]=fmaf(a.x,w.w,acc[0][3]);
    acc[1][0]=fmaf(a.y,w.x,acc[1][0]); acc[1][1]=fmaf(a.y,w.y,acc[1][1]);
    acc[1][2]=fmaf(a.y,w.z,acc[1][2]); acc[1][3]=fmaf(a.y,w.w,acc[1][3]);
    acc[2][0]=fmaf(a.z,w.x,acc[2][0]); acc[2][1]=fmaf(a.z,w.y,acc[2][1]);
    acc[2][2]=fmaf(a.z,w.z,acc[2][2]); acc[2][3]=fmaf(a.z,w.w,acc[2][3]);
    acc[3][0]=fmaf(a.w,w.x,acc[3][0]); acc[3][1]=fmaf(a.w,w.y,acc[3][1]);
    acc[3][2]=fmaf(a.w,w.z,acc[3][2]); acc[3][3]=fmaf(a.w,w.w,acc[3][3]);
}

// ---------------- addressing GEMM: g_w[6144,64] = ktab[q] @ Mk^T -------------
__device__ void stage_addr(float* sm, const float* __restrict__ Mk,
                           const float* __restrict__ ktab, const int* __restrict__ q)
{
    float* As = sm + OFF_AS;      // [32][68]
    float* Ws = sm + OFF_WS;      // [32][36]
    float* part = sm + OFF_PART;  // [4][64][36]
    const int tid = threadIdx.x;
    const int s = tid >> 7, pos = tid & 127, rg = pos >> 3, cg = pos & 7;
    for (int tile = blockIdx.x; tile < 192; tile += NBLK) {
        const int row0 = (tile >> 1) * 64, cc0 = (tile & 1) * 32;
        float acc[4][4] = {};
#pragma unroll 1
        for (int ch = 0; ch < 16; ch++) {
            const int kb = ch * 32;
            {
                int rr = tid >> 3, kq = tid & 7;
                int qi = q[row0 + rr];
                float4 v = *(const float4*)(ktab + (size_t)qi * Dm + kb + kq * 4);
                float* a = As + (kq * 4) * 68 + rr;
                a[0] = v.x; a[68] = v.y; a[136] = v.z; a[204] = v.w;
            }
            if (tid < 256) {
                int n = tid >> 3, kq = tid & 7;
                float4 v = *(const float4*)(Mk + (size_t)(cc0 + n) * Dm + kb + kq * 4);
                float* w = Ws + (kq * 4) * 36 + n;
                w[0] = v.x; w[36] = v.y; w[72] = v.z; w[108] = v.w;
            }
            __syncthreads();
#pragma unroll
            for (int kk = 0; kk < 8; kk++) {
                int k = s * 8 + kk;
                float4 a4 = *(const float4*)(As + k * 68 + rg * 4);
                float4 w4 = *(const float4*)(Ws + k * 36 + cg * 4);
                fma16(acc, a4, w4);
            }
            __syncthreads();
        }
#pragma unroll
        for (int j = 0; j < 4; j++)
            *(float4*)(part + s * 2304 + (rg * 4 + j) * 36 + cg * 4) =
                make_float4(acc[j][0], acc[j][1], acc[j][2], acc[j][3]);
        __syncthreads();
        {
            int rr = tid >> 3, cgx = tid & 7;
            float4 v = make_float4(0.f, 0.f, 0.f, 0.f);
#pragma unroll
            for (int p = 0; p < 4; p++) {
                float4 u = *(const float4*)(part + p * 2304 + rr * 36 + cgx * 4);
                v.x += u.x; v.y += u.y; v.z += u.z; v.w += u.w;
            }
            *(float4*)(g_w + (size_t)(row0 + rr) * 64 + cc0 + cgx * 4) = v;
        }
        __syncthreads();
    }
}

// ---------------- softmax + triangular membership codes ----------------------
__device__ void stage_softmax(float* sm)
{
    unsigned char* ivb = (unsigned char*)(sm + OFF_WT);  // [16][64]
    const int wp = threadIdx.x >> 5, lane = threadIdx.x & 31;
    for (int rr = wp; rr < 48; rr += 16) {
        const int row = blockIdx.x * 48 + rr;
        float v0 = g_w[row * 64 + lane];
        float v1 = g_w[row * 64 + 32 + lane];
        float mx = fmaxf(v0, v1);
        for (int o = 16; o; o >>= 1) mx = fmaxf(mx, __shfl_xor_sync(0xffffffffu, mx, o));
        float e0 = expf(v0 - mx), e1 = expf(v1 - mx);
        float ss = e0 + e1;
        for (int o = 16; o; o >>= 1) ss += __shfl_xor_sync(0xffffffffu, ss, o);
        float inv = 1.0f / ss;
        float w0 = e0 * inv, w1 = e1 * inv;
        g_w[row * 64 + lane] = w0;
        g_w[row * 64 + 32 + lane] = w1;
        auto ivf = [](float w) -> int {
            float m = fmaxf(fminf((w - 0.075f) / (0.088f - 0.075f),
                                  (1.0f - w) / (1.0f - 0.088f)), 0.0f);
            return (m >= 0.6f) ? 2 : ((m >= 0.1f) ? 1 : 0);
        };
        ivb[wp * 64 + lane] = (unsigned char)ivf(w0);
        ivb[wp * 64 + 32 + lane] = (unsigned char)ivf(w1);
        __syncwarp();
        if (lane == 0) {
            unsigned long long c0 = 0ull, c1 = 0ull;
            for (int i = 0; i < 32; i++) {
                c0 |= (unsigned long long)ivb[wp * 64 + i] << (2 * i);
                c1 |= (unsigned long long)ivb[wp * 64 + 32 + i] << (2 * i);
            }
            g_code[row * 2] = c0;
            g_code[row * 2 + 1] = c1;
        }
        __syncwarp();
    }
}

// ---------------- src scan + memS / H0 / C0 / read_0 init --------------------
__device__ void stage_init(float* sm, const float* __restrict__ Mv0,
                           const float* __restrict__ hx0, const float* __restrict__ cx0,
                           int r0, int c0)
{
    float* memS = sm;
    float* wT = sm + OFF_WT;
    const int tid = threadIdx.x;
    if (tid < Tlen) {
        const int b = blockIdx.x, i = tid;
        unsigned long long cc0 = g_code[(b * Tlen + i) * 2];
        unsigned long long cc1 = g_code[(b * Tlen + i) * 2 + 1];
        int sv = i - 1;
        for (int j = i - 1; j >= 0; j--)
            if (g_code[(b * Tlen + j) * 2] == cc0 && g_code[(b * Tlen + j) * 2 + 1] == cc1) { sv = j; break; }
        g_src[b * Tlen + i] = sv;
    }
    for (int i = tid; i < 32768; i += NTHR) {
        int m = (i >> 5) & 63, cc = i & 31;
        memS[i] = Mv0[m * Dm + c0 + cc];
    }
    for (int i = tid; i < 1024; i += NTHR) {
        int bl = i >> 6, m = i & 63;
        wT[i] = g_w[((r0 + bl) * Tlen) * 64 + m];
    }
    __syncthreads();
    const int rr = tid >> 5, cc = tid & 31;
    const int b = r0 + rr, col = c0 + cc;
    g_H[(size_t)b * Dm + col] = hx0[col];
    g_C[(size_t)b * Dm + col] = cx0[col];
    float racc = 0.f;
#pragma unroll 4
    for (int m = 0; m < 64; m++)
        racc = fmaf(wT[rr * 64 + m], memS[(rr * 64 + m) * 32 + cc], racc);
    g_read[(size_t)b * Dm + col] = racc;
}

// ---------------- f / we GEMM (K=1024, 4x4 micro, 16-way split-K) ------------
template<int MODE>   // 0: f = tanh(.), X=g_read, tab=ktab ; 1: we = raw, X=g_f, tab=xtab
__device__ void stage_fwe(float* sm, const float* __restrict__ W, const float* __restrict__ bias,
                          const float* __restrict__ tab, const int* __restrict__ q,
                          const int* __restrict__ r, int t, int r0, int c0)
{
    float* As = sm + OFF_AS;      // per group g: [32][20] at g*640
    float* Ws = sm + OFF_WS;      // per group g: [32][36] at g*1152
    float* part = sm + OFF_PART;  // [16][16][36]
    int* sQ = (int*)(sm + OFF_I16);
    const int tid = threadIdx.x;
    const int g = tid >> 7, gt = tid & 127;
    const int s = gt >> 5, pos = gt & 31, rg = pos >> 3, cg = pos & 7;
    if (tid < 16) {
        int b = r0 + tid;
        int qi = q[b * Tlen + t];
        sQ[tid] = (MODE == 0) ? qi : (qi + 2000 * r[b * Tlen + t]);
    }
    __syncthreads();
    const float* X = (MODE == 0) ? g_read : g_f;
    float acc[4][4] = {};
#pragma unroll 1
    for (int ch = 0; ch < 8; ch++) {
        const int kb = g * 256 + ch * 32;
        {
            int rr = gt >> 3, kq = gt & 7;
            const float* srcp = (g < 2)
                ? X + (size_t)(r0 + rr) * Dm + kb + kq * 4
                : tab + (size_t)sQ[rr] * Dm + (kb - Dm) + kq * 4;
            float4 v = *(const float4*)srcp;
            float* a = As + g * 640 + (kq * 4) * 20 + rr;
            a[0] = v.x; a[20] = v.y; a[40] = v.z; a[60] = v.w;
        }
#pragma unroll
        for (int h = 0; h < 2; h++) {
            int i2 = gt * 2 + h;
            int n = i2 >> 3, kq = i2 & 7;
            float4 v = *(const float4*)(W + (size_t)(c0 + n) * 1024 + kb + kq * 4);
            float* w = Ws + g * 1152 + (kq * 4) * 36 + n;
            w[0] = v.x; w[36] = v.y; w[72] = v.z; w[108] = v.w;
        }
        __syncthreads();
#pragma unroll
        for (int kk = 0; kk < 8; kk++) {
            int k = s * 8 + kk;
            float4 a4 = *(const float4*)(As + g * 640 + k * 20 + rg * 4);
            float4 w4 = *(const float4*)(Ws + g * 1152 + k * 36 + cg * 4);
            fma16(acc, a4, w4);
        }
        __syncthreads();
    }
    const int sid = g * 4 + s;
#pragma unroll
    for (int j = 0; j < 4; j++)
        *(float4*)(part + sid * 576 + (rg * 4 + j) * 36 + cg * 4) =
            make_float4(acc[j][0], acc[j][1], acc[j][2], acc[j][3]);
    __syncthreads();
    {
        const int rr = tid >> 5, cc = tid & 31;
        float v = 0.f;
#pragma unroll
        for (int p = 0; p < 16; p++) v += part[p * 576 + rr * 36 + cc];
        v += bias[c0 + cc];
        const int b = r0 + rr;
        if (MODE == 0) {
            v = tanhf(v);
            g_f[(size_t)b * Dm + c0 + cc] = v;
            g_ft[((size_t)t * Bsz + b) * Dm + c0 + cc] = v;
        } else {
            g_we[(size_t)b * Dm + c0 + cc] = v;
        }
    }
}

// ---------------- e/a GEMMs + smem-resident memory update + read_{t+1} -------
__device__ void stage_ea(float* sm, const float* __restrict__ We, const float* __restrict__ be,
                         const float* __restrict__ Wa, const float* __restrict__ ba,
                         int t, int r0, int c0)
{
    float* memS = sm;
    float* As = sm + OFF_AS;
    float* Ws = sm + OFF_WS;
    float* part = sm + OFF_PART;
    float* wT = sm + OFF_WT;
    float* wN = sm + OFF_WN;
    const int tid = threadIdx.x;
    const int g = tid >> 7, gt = tid & 127;
    const int s = gt >> 5, pos = gt & 31, rg = pos >> 3, cg = pos & 7;
    for (int i = tid; i < 1024; i += NTHR) {
        int bl = i >> 6, m = i & 63;
        wT[i] = g_w[((r0 + bl) * Tlen + t) * 64 + m];
        wN[i] = (t + 1 < Tlen) ? g_w[((r0 + bl) * Tlen + t + 1) * 64 + m] : 0.0f;
    }
    const float* W = (g < 2) ? We : Wa;
    float acc[4][4] = {};
#pragma unroll 1
    for (int ch = 0; ch < 8; ch++) {
        const int kb = (g & 1) * 256 + ch * 32;
        {
            int rr = gt >> 3, kq = gt & 7;
            float4 v = *(const float4*)(g_we + (size_t)(r0 + rr) * Dm + kb + kq * 4);
            float* a = As + g * 640 + (kq * 4) * 20 + rr;
            a[0] = v.x; a[20] = v.y; a[40] = v.z; a[60] = v.w;
        }
#pragma unroll
        for (int h = 0; h < 2; h++) {
            int i2 = gt * 2 + h;
            int n = i2 >> 3, kq = i2 & 7;
            float4 v = *(const float4*)(W + (size_t)(c0 + n) * Dm + kb + kq * 4);
            float* w = Ws + g * 1152 + (kq * 4) * 36 + n;
            w[0] = v.x; w[36] = v.y; w[72] = v.z; w[108] = v.w;
        }
        __syncthreads();
#pragma unroll
        for (int kk = 0; kk < 8; kk++) {
            int k = s * 8 + kk;
            float4 a4 = *(const float4*)(As + g * 640 + k * 20 + rg * 4);
            float4 w4 = *(const float4*)(Ws + g * 1152 + k * 36 + cg * 4);
            fma16(acc, a4, w4);
        }
        __syncthreads();
    }
    const int sid = g * 4 + s;
#pragma unroll
    for (int j = 0; j < 4; j++)
        *(float4*)(part + sid * 576 + (rg * 4 + j) * 36 + cg * 4) =
            make_float4(acc[j][0], acc[j][1], acc[j][2], acc[j][3]);
    __syncthreads();
    {
        const int rr = tid >> 5, cc = tid & 31;
        float ve = 0.f, va = 0.f;
#pragma unroll
        for (int p = 0; p < 8; p++)  ve += part[p * 576 + rr * 36 + cc];
#pragma unroll
        for (int p = 8; p < 16; p++) va += part[p * 576 + rr * 36 + cc];
        ve = sigm(ve + be[c0 + cc]);
        va = tanhf(va + ba[c0 + cc]);
        float racc = 0.f;
#pragma unroll 4
        for (int m = 0; m < 64; m++) {
            float wt = wT[rr * 64 + m], wn = wN[rr * 64 + m];
            float* p = &memS[(rr * 64 + m) * 32 + cc];
            float v = *p;
            v = v * (1.0f - wt * ve) + wt * va;
            *p = v;
            racc = fmaf(wn, v, racc);
        }
        g_read[(size_t)(r0 + rr) * Dm + c0 + cc] = racc;
    }
}

// ---------------- hop-LSTM step: [f_t | h_src] @ [Wih|Whh]^T, K=1024 ---------
__device__ void stage_lstm(float* sm, const float* __restrict__ Wih, const float* __restrict__ Whh,
                           const float* __restrict__ bih, const float* __restrict__ bhh,
                           int t, int r0, int c0)
{
    float* As = sm + OFF_AS;      // shared [32][20]
    float* Ws = sm + OFF_WS;
    float* part = sm + OFF_PART;
    int* s16 = (int*)(sm + OFF_I16);
    const int tid = threadIdx.x;
    const int g = tid >> 7, gt = tid & 127;
    const int s = gt >> 5, pos = gt & 31, rg = pos >> 3, cg = pos & 7;
    if (tid < 16) s16[tid] = g_src[(r0 + tid) * Tlen + t] + 1;
    __syncthreads();
    float acc[4][4] = {};
#pragma unroll 1
    for (int ch = 0; ch < 32; ch++) {
        const int kb = ch * 32;
        if (g == 0) {
            int rr = gt >> 3, kq = gt & 7;
            const float* srcp = (kb < Dm)
                ? g_ft + ((size_t)t * Bsz + r0 + rr) * Dm + kb + kq * 4
                : g_H + ((size_t)s16[rr] * Bsz + r0 + rr) * Dm + (kb - Dm) + kq * 4;
            float4 v = *(const float4*)srcp;
            float* a = As + (kq * 4) * 20 + rr;
            a[0] = v.x; a[20] = v.y; a[40] = v.z; a[60] = v.w;
        }
#pragma unroll
        for (int h = 0; h < 2; h++) {
            int i2 = gt * 2 + h;
            int n = i2 >> 3, kq = i2 & 7;
            const float* wsrc = (kb < Dm)
                ? Wih + (size_t)(g * Dm + c0 + n) * Dm + kb + kq * 4
                : Whh + (size_t)(g * Dm + c0 + n) * Dm + (kb - Dm) + kq * 4;
            float4 v = *(const float4*)wsrc;
            float* w = Ws + g * 1152 + (kq * 4) * 36 + n;
            w[0] = v.x; w[36] = v.y; w[72] = v.z; w[108] = v.w;
        }
        __syncthreads();
#pragma unroll
        for (int kk = 0; kk < 8; kk++) {
            int k = s * 8 + kk;
            float4 a4 = *(const float4*)(As + k * 20 + rg * 4);
            float4 w4 = *(const float4*)(Ws + g * 1152 + k * 36 + cg * 4);
            fma16(acc, a4, w4);
        }
        __syncthreads();
    }
    const int sid = g * 4 + s;
#pragma unroll
    for (int j = 0; j < 4; j++)
        *(float4*)(part + sid * 576 + (rg * 4 + j) * 36 + cg * 4) =
            make_float4(acc[j][0], acc[j][1], acc[j][2], acc[j][3]);
    __syncthreads();
    {
        const int rr = tid >> 5, cc = tid & 31;
        float gi = 0.f, gf = 0.f, gg = 0.f, go = 0.f;
#pragma unroll
        for (int p = 0; p < 4; p++)   gi += part[p * 576 + rr * 36 + cc];
#pragma unroll
        for (int p = 4; p < 8; p++)   gf += part[p * 576 + rr * 36 + cc];
#pragma unroll
        for (int p = 8; p < 12; p++)  gg += part[p * 576 + rr * 36 + cc];
#pragma unroll
        for (int p = 12; p < 16; p++) go += part[p * 576 + rr * 36 + cc];
        const int b = r0 + rr, col = c0 + cc;
        gi += bih[col] + bhh[col];
        gf += bih[512 + col] + bhh[512 + col];
        gg += bih[1024 + col] + bhh[1024 + col];
        go += bih[1536 + col] + bhh[1536 + col];
        float cin = g_C[((size_t)s16[rr] * Bsz + b) * Dm + col];
        float cn = sigm(gf) * cin + sigm(gi) * tanhf(gg);
        float hn = sigm(go) * tanhf(cn);
        g_C[((size_t)(t + 1) * Bsz + b) * Dm + col] = cn;
        g_H[((size_t)(t + 1) * Bsz + b) * Dm + col] = hn;
    }
}

// ---------------- prediction head --------------------------------------------
__device__ void stage_head(const float* __restrict__ Wp, const float* __restrict__ bp,
                           float* __restrict__ out)
{
    const int wp = threadIdx.x >> 5, lane = threadIdx.x & 31;
    for (int bt = blockIdx.x * 16 + wp; bt < Bsz * Tlen; bt += NBLK * 16) {
        const int b = bt / Tlen, t = bt % Tlen;
        const float* h = &g_H[((size_t)(t + 1) * Bsz + b) * Dm];
        float s = 0.f;
        for (int i = lane; i < Dm; i += 32) s = fmaf(h[i], Wp[i], s);
        for (int o = 16; o; o >>= 1) s += __shfl_xor_sync(0xffffffffu, s, o);
        if (lane == 0) out[bt] = sigm(s + bp[0]);
    }
}

// ---------------- the single persistent kernel -------------------------------
__global__ void __launch_bounds__(NTHR, 1) k_persist(
    const int* __restrict__ q, const int* __restrict__ r,
    const float* __restrict__ Mk, const float* __restrict__ Mv0,
    const float* __restrict__ ktab, const float* __restrict__ xtab,
    const float* __restrict__ We, const float* __restrict__ be,
    const float* __restrict__ Wadd, const float* __restrict__ badd,
    const float* __restrict__ Wa, const float* __restrict__ ba,
    const float* __restrict__ Wf, const float* __restrict__ bf,
    const float* __restrict__ Wih, const float* __restrict__ Whh,
    const float* __restrict__ bih, const float* __restrict__ bhh,
    const float* __restrict__ hx0, const float* __restrict__ cx0,
    const float* __restrict__ Wp, const float* __restrict__ bp,
    float* __restrict__ out)
{
    extern __shared__ float sm[];
    unsigned ls = 0;
    if (threadIdx.x == 0) ls = g_sense;
    const int r0 = (blockIdx.x & 7) * 16;
    const int c0 = (blockIdx.x >> 3) * 32;

    stage_addr(sm, Mk, ktab, q);                          gsync(ls);
    stage_softmax(sm);                                    gsync(ls);
    stage_init(sm, Mv0, hx0, cx0, r0, c0);                gsync(ls);

    for (int t = 0; t < Tlen; t++) {
        stage_fwe<0>(sm, Wf, bf, ktab, q, r, t, r0, c0);  gsync(ls);
        stage_fwe<1>(sm, Wa, ba, xtab, q, r, t, r0, c0);  gsync(ls);
        stage_ea(sm, We, be, Wadd, badd, t, r0, c0);      gsync(ls);
    }
    for (int t = 0; t < Tlen; t++) {
        stage_lstm(sm, Wih, Whh, bih, bhh, t, r0, c0);    gsync(ls);
    }
    stage_head(Wp, bp, out);
}

// ----------------------------------------------------------------------------
extern "C" void kernel_launch(void* const* d_in, const int* in_sizes, int n_in,
                              void* d_out, int out_size)
{
    const int*   q    = (const int*)d_in[0];
    const int*   r    = (const int*)d_in[1];
    const float* Mk   = (const float*)d_in[2];
    const float* Mv0  = (const float*)d_in[3];
    const float* ktab = (const float*)d_in[4];
    const float* xtab = (const float*)d_in[5];
    const float* We   = (const float*)d_in[6];
    const float* be   = (const float*)d_in[7];
    const float* Wadd = (const float*)d_in[8];
    const float* badd = (const float*)d_in[9];
    const float* Wa   = (const float*)d_in[10];
    const float* ba   = (const float*)d_in[11];
    const float* Wf   = (const float*)d_in[12];
    const float* bf   = (const float*)d_in[13];
    const float* Wih  = (const float*)d_in[14];
    const float* Whh  = (const float*)d_in[15];
    const float* bih  = (const float*)d_in[16];
    const float* bhh  = (const float*)d_in[17];
    const float* hx0  = (const float*)d_in[18];
    const float* cx0  = (const float*)d_in[19];
    const float* Wp   = (const float*)d_in[20];
    const float* bp   = (const float*)d_in[21];
    float* out = (float*)d_out;

    static bool attr_set = false;
    if (!attr_set) {
        cudaFuncSetAttribute(k_persist, cudaFuncAttributeMaxDynamicSharedMemorySize, SMEM_BYTES);
        attr_set = true;
    }
    k_persist<<<NBLK, NTHR, SMEM_BYTES>>>(q, r, Mk, Mv0, ktab, xtab, We, be, Wadd, badd,
                                          Wa, ba, Wf, bf, Wih, Whh, bih, bhh,
                                          hx0, cx0, Wp, bp, out);
}